// round 1
// baseline (speedup 1.0000x reference)
#include <cuda_runtime.h>
#include <cstdint>

typedef unsigned long long u64;

#define NB 4096
#define NE 16
#define ND 512
#define NH 2048

#define BM 128
#define BN 128
#define BK 16

// Scratch: combined per-expert bias  d[e,h] = b[e,h] - dot(c_e, W[e,h,:])
__device__ float g_dcomb[NE * NH];

// ---------------------------------------------------------------------------
// Kernel A: one warp per (e,h) row — 32768 rows, 512-length dot each.
// ---------------------------------------------------------------------------
__global__ void bias_kernel(const float* __restrict__ centers,
                            const float* __restrict__ W,
                            const float* __restrict__ bias) {
    int gw   = (blockIdx.x * blockDim.x + threadIdx.x) >> 5;
    int lane = threadIdx.x & 31;
    if (gw >= NE * NH) return;
    int e = gw >> 11;  // / NH
    const float* wr = W + (size_t)gw * ND;
    const float* cr = centers + e * ND;
    float s = 0.f;
#pragma unroll
    for (int i = 0; i < ND / 32; i++)
        s += cr[lane + 32 * i] * wr[lane + 32 * i];
#pragma unroll
    for (int o = 16; o; o >>= 1)
        s += __shfl_xor_sync(0xffffffffu, s, o);
    if (lane == 0) g_dcomb[gw] = bias[gw] - s;
}

// ---------------------------------------------------------------------------
// Packed fp32x2 FMA (Blackwell FFMA2 — only reachable via PTX fma.rn.f32x2)
// ---------------------------------------------------------------------------
__device__ __forceinline__ u64 ffma2(u64 a, u64 b, u64 c) {
    u64 d;
    asm("fma.rn.f32x2 %0, %1, %2, %3;" : "=l"(d) : "l"(a), "l"(b), "l"(c));
    return d;
}
__device__ __forceinline__ u64 dup2(float v) {
    u64 u = (u64)__float_as_uint(v);
    return u | (u << 32);
}

// ---------------------------------------------------------------------------
// Kernel B: fused expert GEMM.
// Grid (NH/BN, NB/BM) = (16, 32). 256 threads, 8x8 microtile (4 f32x2 pairs).
// For each expert: acc = x_tile @ W_e_tile^T  (K=512), then
// out += relu(acc + d[e, h]).
// ---------------------------------------------------------------------------
__global__ void __launch_bounds__(256, 1)
fused_kernel(const float* __restrict__ x,
             const float* __restrict__ W,
             float* __restrict__ out) {
    __shared__ u64   As2[BK][BM];   // x tile, each value duplicated into both f32x2 lanes (16 KB)
    __shared__ float Bs [BK][BN];   // W tile, [k][n] (8 KB)

    const int tid  = threadIdx.x;
    const int tx   = tid & 15, ty = tid >> 4;
    const int m0   = ty * 8,  n0 = tx * 8;
    const int mb   = blockIdx.y * BM, hb = blockIdx.x * BN;
    const int r    = tid >> 1;      // 0..127: which row of the tile this thread loads
    const int half = tid & 1;       // which 8-float chunk of the 16-wide k slice
    const int kk0  = half * 8;

    const float* xrow = x + (size_t)(mb + r) * ND + half * 8;

    float outacc[8][8];
#pragma unroll
    for (int i = 0; i < 8; i++)
#pragma unroll
        for (int j = 0; j < 8; j++) outacc[i][j] = 0.f;

    for (int e = 0; e < NE; e++) {
        const float* wrow = W + (size_t)(e * NH + hb + r) * ND + half * 8;

        u64 acc[8][4];
#pragma unroll
        for (int i = 0; i < 8; i++)
#pragma unroll
            for (int j = 0; j < 4; j++) acc[i][j] = 0ull;

        // register prefetch of first k-tile
        float4 xa = *(const float4*)(xrow + 0);
        float4 xb = *(const float4*)(xrow + 4);
        float4 wa = *(const float4*)(wrow + 0);
        float4 wb = *(const float4*)(wrow + 4);

        for (int k0 = 0; k0 < ND; k0 += BK) {
            As2[kk0 + 0][r] = dup2(xa.x);
            As2[kk0 + 1][r] = dup2(xa.y);
            As2[kk0 + 2][r] = dup2(xa.z);
            As2[kk0 + 3][r] = dup2(xa.w);
            As2[kk0 + 4][r] = dup2(xb.x);
            As2[kk0 + 5][r] = dup2(xb.y);
            As2[kk0 + 6][r] = dup2(xb.z);
            As2[kk0 + 7][r] = dup2(xb.w);
            Bs[kk0 + 0][r] = wa.x;
            Bs[kk0 + 1][r] = wa.y;
            Bs[kk0 + 2][r] = wa.z;
            Bs[kk0 + 3][r] = wa.w;
            Bs[kk0 + 4][r] = wb.x;
            Bs[kk0 + 5][r] = wb.y;
            Bs[kk0 + 6][r] = wb.z;
            Bs[kk0 + 7][r] = wb.w;
            __syncthreads();

            if (k0 + BK < ND) {  // prefetch next k-tile while computing this one
                xa = *(const float4*)(xrow + k0 + BK + 0);
                xb = *(const float4*)(xrow + k0 + BK + 4);
                wa = *(const float4*)(wrow + k0 + BK + 0);
                wb = *(const float4*)(wrow + k0 + BK + 4);
            }

#pragma unroll
            for (int kk = 0; kk < BK; kk++) {
                u64 a2[8], b2[4];
                const ulonglong2* ap = (const ulonglong2*)&As2[kk][m0];
                ulonglong2 t0 = ap[0], t1 = ap[1], t2 = ap[2], t3 = ap[3];
                a2[0] = t0.x; a2[1] = t0.y; a2[2] = t1.x; a2[3] = t1.y;
                a2[4] = t2.x; a2[5] = t2.y; a2[6] = t3.x; a2[7] = t3.y;
                const ulonglong2* bp = (const ulonglong2*)&Bs[kk][n0];
                ulonglong2 u0 = bp[0], u1 = bp[1];
                b2[0] = u0.x; b2[1] = u0.y; b2[2] = u1.x; b2[3] = u1.y;
#pragma unroll
                for (int i = 0; i < 8; i++)
#pragma unroll
                    for (int j = 0; j < 4; j++)
                        acc[i][j] = ffma2(a2[i], b2[j], acc[i][j]);
            }
            __syncthreads();
        }

        // per-expert epilogue: relu(acc + d) accumulated into outacc
        const float4* dcp = (const float4*)(g_dcomb + e * NH + hb + n0);
        float4 d0 = dcp[0], d1 = dcp[1];
        float dcv[8] = {d0.x, d0.y, d0.z, d0.w, d1.x, d1.y, d1.z, d1.w};
#pragma unroll
        for (int i = 0; i < 8; i++)
#pragma unroll
            for (int j = 0; j < 4; j++) {
                float lo = __uint_as_float((unsigned)(acc[i][j] & 0xffffffffull));
                float hi = __uint_as_float((unsigned)(acc[i][j] >> 32));
                outacc[i][2 * j + 0] += fmaxf(lo + dcv[2 * j + 0], 0.f);
                outacc[i][2 * j + 1] += fmaxf(hi + dcv[2 * j + 1], 0.f);
            }
    }

#pragma unroll
    for (int i = 0; i < 8; i++) {
        float* op = out + (size_t)(mb + m0 + i) * NH + hb + n0;
        *(float4*)(op + 0) = make_float4(outacc[i][0], outacc[i][1], outacc[i][2], outacc[i][3]);
        *(float4*)(op + 4) = make_float4(outacc[i][4], outacc[i][5], outacc[i][6], outacc[i][7]);
    }
}

// ---------------------------------------------------------------------------
// Launch
// ---------------------------------------------------------------------------
extern "C" void kernel_launch(void* const* d_in, const int* in_sizes, int n_in,
                              void* d_out, int out_size) {
    const float* x       = (const float*)d_in[0];  // [B, D]
    const float* centers = (const float*)d_in[1];  // [E, D]
    const float* W       = (const float*)d_in[2];  // [E, H, D]
    const float* bias    = (const float*)d_in[3];  // [E, H]
    float* out = (float*)d_out;                    // [B, H]

    // d[e,h] = b[e,h] - c_e . W[e,h,:]
    bias_kernel<<<(NE * NH) / 8, 256>>>(centers, W, bias);

    dim3 grid(NH / BN, NB / BM);   // (16, 32)
    fused_kernel<<<grid, 256>>>(x, W, out);
}

// round 3
// speedup vs baseline: 4.1217x; 4.1217x over previous
#include <cuda_runtime.h>
#include <cuda_bf16.h>
#include <cstdint>

typedef unsigned long long u64;
typedef uint32_t u32;

#define NB 4096
#define NE 16
#define ND 512
#define NH 2048

#define KC 64                          // k-chunk: 64 bf16 = 128B rows
#define TILE 16384                     // 128 x 64 bf16 tile bytes
#define STAGE (4 * TILE)               // xh, xl, wh, wl
#define NSTAGE 3
#define OFF_STAGES 8192                // after d-table (16*128 floats)
#define SMEM_TOTAL (OFF_STAGES + NSTAGE * STAGE)   // 204800 B

// ---------------- scratch (device globals; no allocations allowed) ----------
__device__ __nv_bfloat16 g_xhi[NB * ND];
__device__ __nv_bfloat16 g_xlo[NB * ND];
__device__ __nv_bfloat16 g_whi[NE * NH * ND];
__device__ __nv_bfloat16 g_wlo[NE * NH * ND];
__device__ float         g_dcomb[NE * NH];

// ---------------- PTX helpers ----------------------------------------------
__device__ __forceinline__ u32 smem_u32(const void* p) {
    u32 a;
    asm("{ .reg .u64 t; cvta.to.shared.u64 t, %1; cvt.u32.u64 %0, t; }" : "=r"(a) : "l"(p));
    return a;
}
__device__ __forceinline__ void cp16(u32 dst, const void* src) {
    asm volatile("cp.async.cg.shared.global [%0], [%1], 16;" :: "r"(dst), "l"(src) : "memory");
}
__device__ __forceinline__ void cp_commit() { asm volatile("cp.async.commit_group;" ::: "memory"); }
__device__ __forceinline__ void cp_wait2()  { asm volatile("cp.async.wait_group 2;" ::: "memory"); }

__device__ __forceinline__ void ldsm4(u32& r0, u32& r1, u32& r2, u32& r3, u32 addr) {
    asm volatile("ldmatrix.sync.aligned.m8n8.x4.shared.b16 {%0,%1,%2,%3}, [%4];"
                 : "=r"(r0), "=r"(r1), "=r"(r2), "=r"(r3) : "r"(addr));
}
__device__ __forceinline__ void mma16816(float* c, const u32* a, const u32* b) {
    asm volatile("mma.sync.aligned.m16n8k16.row.col.f32.bf16.bf16.f32 "
                 "{%0,%1,%2,%3}, {%4,%5,%6,%7}, {%8,%9}, {%0,%1,%2,%3};"
                 : "+f"(c[0]), "+f"(c[1]), "+f"(c[2]), "+f"(c[3])
                 : "r"(a[0]), "r"(a[1]), "r"(a[2]), "r"(a[3]), "r"(b[0]), "r"(b[1]));
}

__device__ __forceinline__ u32 swz128(u32 off) { return off ^ ((off >> 3) & 0x70); }

// ---------------- prep kernels ----------------------------------------------
__device__ __forceinline__ void split2(float f, __nv_bfloat16& hi, __nv_bfloat16& lo) {
    hi = __float2bfloat16_rn(f);
    lo = __float2bfloat16_rn(f - __bfloat162float(hi));
}

__global__ void x_split_kernel(const float* __restrict__ x) {
    int i = blockIdx.x * blockDim.x + threadIdx.x;
    float4 v = ((const float4*)x)[i];
    __nv_bfloat16 h0, l0, h1, l1, h2, l2, h3, l3;
    split2(v.x, h0, l0); split2(v.y, h1, l1); split2(v.z, h2, l2); split2(v.w, h3, l3);
    __nv_bfloat162* ph = (__nv_bfloat162*)g_xhi;
    __nv_bfloat162* pl = (__nv_bfloat162*)g_xlo;
    ph[2 * i]     = __nv_bfloat162(h0, h1);
    ph[2 * i + 1] = __nv_bfloat162(h2, h3);
    pl[2 * i]     = __nv_bfloat162(l0, l1);
    pl[2 * i + 1] = __nv_bfloat162(l2, l3);
}

__global__ void w_split_bias_kernel(const float* __restrict__ W,
                                    const float* __restrict__ centers,
                                    const float* __restrict__ bias) {
    int gw   = (blockIdx.x * blockDim.x + threadIdx.x) >> 5;
    int lane = threadIdx.x & 31;
    if (gw >= NE * NH) return;
    int e = gw >> 11;
    const float4* wr = (const float4*)(W + (size_t)gw * ND);
    const float4* cr = (const float4*)(centers + (size_t)e * ND);
    __nv_bfloat162* ph = (__nv_bfloat162*)(g_whi + (size_t)gw * ND);
    __nv_bfloat162* pl = (__nv_bfloat162*)(g_wlo + (size_t)gw * ND);
    float s = 0.f;
#pragma unroll
    for (int i = 0; i < ND / 128; i++) {
        int idx = lane + 32 * i;
        float4 w4 = wr[idx];
        float4 c4 = cr[idx];
        s += w4.x * c4.x + w4.y * c4.y + w4.z * c4.z + w4.w * c4.w;
        __nv_bfloat16 h0, l0, h1, l1, h2, l2, h3, l3;
        split2(w4.x, h0, l0); split2(w4.y, h1, l1);
        split2(w4.z, h2, l2); split2(w4.w, h3, l3);
        ph[2 * idx]     = __nv_bfloat162(h0, h1);
        ph[2 * idx + 1] = __nv_bfloat162(h2, h3);
        pl[2 * idx]     = __nv_bfloat162(l0, l1);
        pl[2 * idx + 1] = __nv_bfloat162(l2, l3);
    }
#pragma unroll
    for (int o = 16; o; o >>= 1) s += __shfl_xor_sync(0xffffffffu, s, o);
    if (lane == 0) g_dcomb[gw] = bias[gw] - s;
}

// ---------------- main GEMM kernel -------------------------------------------
// grid (NH/128, NB/128) = (16, 32); 256 threads, 8 warps (2m x 4n of 64x32).
// 128 chunks = 16 experts x 8 k-chunks of 64. 3-term bf16 split per k16 step.

__device__ __forceinline__ void load_chunk(int gc, u32 dst, int mb, int hb, int tid) {
    int e = gc >> 3, kc = (gc & 7) * KC;
    int row = tid >> 3, c = tid & 7;
    u32 so = swz128((u32)(row * 128 + c * 16));
    const __nv_bfloat16* pxh = g_xhi + (size_t)(mb + row) * ND + kc + c * 8;
    const __nv_bfloat16* pxl = g_xlo + (size_t)(mb + row) * ND + kc + c * 8;
    const __nv_bfloat16* pwh = g_whi + (size_t)(e * NH + hb + row) * ND + kc + c * 8;
    const __nv_bfloat16* pwl = g_wlo + (size_t)(e * NH + hb + row) * ND + kc + c * 8;
#pragma unroll
    for (int i = 0; i < 4; i++) {
        u32 d = dst + so + (u32)i * 4096;          // +32 rows per step
        size_t eo = (size_t)(32 * i) * ND;
        cp16(d + 0 * TILE, pxh + eo);
        cp16(d + 1 * TILE, pxl + eo);
        cp16(d + 2 * TILE, pwh + eo);
        cp16(d + 3 * TILE, pwl + eo);
    }
}

__global__ void __launch_bounds__(256, 1)
gemm_kernel(float* __restrict__ out) {
    extern __shared__ char smem[];
    float* dsm = (float*)smem;                     // [16][128] combined bias
    u32 sb = smem_u32(smem) + OFF_STAGES;
    const int tid = threadIdx.x, wid = tid >> 5, lane = tid & 31;
    const int hb = blockIdx.x * 128, mb = blockIdx.y * 128;
    const int wm = (wid >> 2) * 64, wn = (wid & 3) * 32;

    // stage the per-expert combined bias slice for this CTA
#pragma unroll
    for (int i = tid; i < NE * 128; i += 256)
        dsm[i] = g_dcomb[(size_t)(i >> 7) * NH + hb + (i & 127)];

    load_chunk(0, sb + 0 * STAGE, mb, hb, tid); cp_commit();
    load_chunk(1, sb + 1 * STAGE, mb, hb, tid); cp_commit();
    load_chunk(2, sb + 2 * STAGE, mb, hb, tid); cp_commit();

    float acc[4][4][4], oacc[4][4][4];
#pragma unroll
    for (int a = 0; a < 4; a++)
#pragma unroll
        for (int b = 0; b < 4; b++)
#pragma unroll
            for (int c = 0; c < 4; c++) { acc[a][b][c] = 0.f; oacc[a][b][c] = 0.f; }

    int st_idx = 0;
    for (int gc = 0; gc < 128; gc++) {
        cp_wait2();
        __syncthreads();

        u32 st = sb + (u32)st_idx * STAGE;
        u32 Ah = st, Al = st + TILE, Bh = st + 2 * TILE, Bl = st + 3 * TILE;

#pragma unroll
        for (int ks = 0; ks < 4; ks++) {
            u32 ah[4][4], al[4][4], bh[4][2], bl[4][2];
            u32 arel = swz128((u32)((lane & 15) * 128 + ks * 32 + (lane >> 4) * 16));
#pragma unroll
            for (int mt = 0; mt < 4; mt++) {
                u32 ao = (u32)((wm + mt * 16) * 128) + arel;
                ldsm4(ah[mt][0], ah[mt][1], ah[mt][2], ah[mt][3], Ah + ao);
                ldsm4(al[mt][0], al[mt][1], al[mt][2], al[mt][3], Al + ao);
            }
            u32 brel = swz128((u32)((lane & 7) * 128 + ks * 32 + ((lane >> 3) & 1) * 16));
#pragma unroll
            for (int pr = 0; pr < 2; pr++) {
                u32 bo = (u32)((wn + pr * 16 + ((lane >> 4) & 1) * 8) * 128) + brel;
                ldsm4(bh[pr * 2][0], bh[pr * 2][1], bh[pr * 2 + 1][0], bh[pr * 2 + 1][1], Bh + bo);
                ldsm4(bl[pr * 2][0], bl[pr * 2][1], bl[pr * 2 + 1][0], bl[pr * 2 + 1][1], Bl + bo);
            }
#pragma unroll
            for (int mt = 0; mt < 4; mt++)
#pragma unroll
                for (int nt = 0; nt < 4; nt++) {
                    mma16816(acc[mt][nt], ah[mt], bh[nt]);   // hi*hi
                    mma16816(acc[mt][nt], ah[mt], bl[nt]);   // hi*lo
                    mma16816(acc[mt][nt], al[mt], bh[nt]);   // lo*hi
                }
        }

        if ((gc & 7) == 7) {    // finished expert e: relu + accumulate, reset
            int e = gc >> 3;
            const float2* dp = (const float2*)(dsm + e * 128 + wn);
#pragma unroll
            for (int nt = 0; nt < 4; nt++) {
                float2 d2 = dp[nt * 4 + (lane & 3)];
#pragma unroll
                for (int mt = 0; mt < 4; mt++) {
                    oacc[mt][nt][0] += fmaxf(acc[mt][nt][0] + d2.x, 0.f);
                    oacc[mt][nt][1] += fmaxf(acc[mt][nt][1] + d2.y, 0.f);
                    oacc[mt][nt][2] += fmaxf(acc[mt][nt][2] + d2.x, 0.f);
                    oacc[mt][nt][3] += fmaxf(acc[mt][nt][3] + d2.y, 0.f);
                    acc[mt][nt][0] = 0.f; acc[mt][nt][1] = 0.f;
                    acc[mt][nt][2] = 0.f; acc[mt][nt][3] = 0.f;
                }
            }
        }

        __syncthreads();
        if (gc + 3 < 128) load_chunk(gc + 3, st, mb, hb, tid);
        cp_commit();            // one group per iteration keeps wait_group counting exact
        st_idx = (st_idx == 2) ? 0 : st_idx + 1;
    }

    // store: C fragment mapping — (row t/4 [+8], col 2*(t%4) [+1])
#pragma unroll
    for (int mt = 0; mt < 4; mt++)
#pragma unroll
        for (int nt = 0; nt < 4; nt++) {
            int r0 = mb + wm + mt * 16 + (lane >> 2);
            int cc = hb + wn + nt * 8 + 2 * (lane & 3);
            *(float2*)(out + (size_t)r0 * NH + cc) =
                make_float2(oacc[mt][nt][0], oacc[mt][nt][1]);
            *(float2*)(out + (size_t)(r0 + 8) * NH + cc) =
                make_float2(oacc[mt][nt][2], oacc[mt][nt][3]);
        }
}

// ---------------- launch -----------------------------------------------------
extern "C" void kernel_launch(void* const* d_in, const int* in_sizes, int n_in,
                              void* d_out, int out_size) {
    const float* x       = (const float*)d_in[0];  // [B, D]
    const float* centers = (const float*)d_in[1];  // [E, D]
    const float* W       = (const float*)d_in[2];  // [E, H, D]
    const float* bias    = (const float*)d_in[3];  // [E, H]
    float* out = (float*)d_out;                    // [B, H]

    cudaFuncSetAttribute(gemm_kernel, cudaFuncAttributeMaxDynamicSharedMemorySize, SMEM_TOTAL);

    x_split_kernel<<<(NB * ND / 4) / 256, 256>>>(x);
    w_split_bias_kernel<<<(NE * NH) / 8, 256>>>(W, centers, bias);

    dim3 grid(NH / 128, NB / 128);   // (16, 32)
    gemm_kernel<<<grid, 256, SMEM_TOTAL>>>(out);
}

// round 4
// speedup vs baseline: 5.5787x; 1.3535x over previous
#include <cuda_runtime.h>
#include <cuda_fp16.h>
#include <cstdint>

typedef unsigned long long u64;
typedef uint32_t u32;

#define NB 4096
#define NE 16
#define ND 512
#define NH 2048

#define KC 64                          // k-chunk: 64 fp16 = 128B rows
#define TILE 16384                     // 128 x 64 fp16 tile bytes
#define STAGE (3 * TILE)               // xh, wh, wl
#define NSTAGE 4
#define OFF_STAGES 8192                // after d-table (16*128 floats)
#define SMEM_TOTAL (OFF_STAGES + NSTAGE * STAGE)   // 204800 B

#define WSCALE 32.0f
#define INV_WSCALE 0.03125f

// ---------------- scratch (device globals; no allocations allowed) ----------
__device__ __half g_xhi[NB * ND];
__device__ __half g_whi[NE * NH * ND];
__device__ __half g_wlo[NE * NH * ND];
__device__ float  g_dcomb[NE * NH];

// ---------------- PTX helpers ----------------------------------------------
__device__ __forceinline__ u32 smem_u32(const void* p) {
    u32 a;
    asm("{ .reg .u64 t; cvta.to.shared.u64 t, %1; cvt.u32.u64 %0, t; }" : "=r"(a) : "l"(p));
    return a;
}
__device__ __forceinline__ void cp16(u32 dst, const void* src) {
    asm volatile("cp.async.cg.shared.global [%0], [%1], 16;" :: "r"(dst), "l"(src) : "memory");
}
__device__ __forceinline__ void cp_commit() { asm volatile("cp.async.commit_group;" ::: "memory"); }
__device__ __forceinline__ void cp_wait2()  { asm volatile("cp.async.wait_group 2;" ::: "memory"); }

__device__ __forceinline__ void ldsm4(u32& r0, u32& r1, u32& r2, u32& r3, u32 addr) {
    asm volatile("ldmatrix.sync.aligned.m8n8.x4.shared.b16 {%0,%1,%2,%3}, [%4];"
                 : "=r"(r0), "=r"(r1), "=r"(r2), "=r"(r3) : "r"(addr));
}
__device__ __forceinline__ void mma16816(float* c, const u32* a, const u32* b) {
    asm volatile("mma.sync.aligned.m16n8k16.row.col.f32.f16.f16.f32 "
                 "{%0,%1,%2,%3}, {%4,%5,%6,%7}, {%8,%9}, {%0,%1,%2,%3};"
                 : "+f"(c[0]), "+f"(c[1]), "+f"(c[2]), "+f"(c[3])
                 : "r"(a[0]), "r"(a[1]), "r"(a[2]), "r"(a[3]), "r"(b[0]), "r"(b[1]));
}

__device__ __forceinline__ u32 swz128(u32 off) { return off ^ ((off >> 3) & 0x70); }

// ---------------- prep kernels ----------------------------------------------
__global__ void x_split_kernel(const float* __restrict__ x) {
    int i = blockIdx.x * blockDim.x + threadIdx.x;
    float4 v = ((const float4*)x)[i];
    __half2* ph = (__half2*)g_xhi;
    ph[2 * i]     = __half2(__float2half_rn(v.x), __float2half_rn(v.y));
    ph[2 * i + 1] = __half2(__float2half_rn(v.z), __float2half_rn(v.w));
}

// one warp per (e,h) row: split 32*W row into fp16 hi/lo and d = bias - c_e . W_row
__global__ void w_split_bias_kernel(const float* __restrict__ W,
                                    const float* __restrict__ centers,
                                    const float* __restrict__ bias) {
    int gw   = (blockIdx.x * blockDim.x + threadIdx.x) >> 5;
    int lane = threadIdx.x & 31;
    if (gw >= NE * NH) return;
    int e = gw >> 11;
    const float4* wr = (const float4*)(W + (size_t)gw * ND);
    const float4* cr = (const float4*)(centers + (size_t)e * ND);
    __half2* ph = (__half2*)(g_whi + (size_t)gw * ND);
    __half2* pl = (__half2*)(g_wlo + (size_t)gw * ND);
    float s = 0.f;
#pragma unroll
    for (int i = 0; i < ND / 128; i++) {
        int idx = lane + 32 * i;
        float4 w4 = wr[idx];
        float4 c4 = cr[idx];
        s += w4.x * c4.x + w4.y * c4.y + w4.z * c4.z + w4.w * c4.w;
        float s0 = w4.x * WSCALE, s1 = w4.y * WSCALE, s2 = w4.z * WSCALE, s3 = w4.w * WSCALE;
        __half h0 = __float2half_rn(s0), h1 = __float2half_rn(s1);
        __half h2 = __float2half_rn(s2), h3 = __float2half_rn(s3);
        __half l0 = __float2half_rn(s0 - __half2float(h0));
        __half l1 = __float2half_rn(s1 - __half2float(h1));
        __half l2 = __float2half_rn(s2 - __half2float(h2));
        __half l3 = __float2half_rn(s3 - __half2float(h3));
        ph[2 * idx]     = __half2(h0, h1);
        ph[2 * idx + 1] = __half2(h2, h3);
        pl[2 * idx]     = __half2(l0, l1);
        pl[2 * idx + 1] = __half2(l2, l3);
    }
#pragma unroll
    for (int o = 16; o; o >>= 1) s += __shfl_xor_sync(0xffffffffu, s, o);
    if (lane == 0) g_dcomb[gw] = bias[gw] - s;
}

// ---------------- main GEMM kernel -------------------------------------------
// grid (NH/128, NB/128) = (16, 32); 256 threads, 8 warps (2m x 4n of 64x32).
// 128 chunks = 16 experts x 8 k-chunks of 64. Per k16: hh + hl fp16 MMAs.

__device__ __forceinline__ void load_chunk(int gc, u32 dst, int mb, int hb, int tid) {
    int e = gc >> 3, kc = (gc & 7) * KC;
    int row = tid >> 3, c = tid & 7;
    u32 so = swz128((u32)(row * 128 + c * 16));
    const __half* pxh = g_xhi + (size_t)(mb + row) * ND + kc + c * 8;
    const __half* pwh = g_whi + (size_t)(e * NH + hb + row) * ND + kc + c * 8;
    const __half* pwl = g_wlo + (size_t)(e * NH + hb + row) * ND + kc + c * 8;
#pragma unroll
    for (int i = 0; i < 4; i++) {
        u32 d = dst + so + (u32)i * 4096;          // +32 rows per step
        size_t eo = (size_t)(32 * i) * ND;
        cp16(d + 0 * TILE, pxh + eo);
        cp16(d + 1 * TILE, pwh + eo);
        cp16(d + 2 * TILE, pwl + eo);
    }
}

__global__ void __launch_bounds__(256, 1)
gemm_kernel(float* __restrict__ out) {
    extern __shared__ char smem[];
    float* dsm = (float*)smem;                     // [16][128] combined bias
    u32 sb = smem_u32(smem) + OFF_STAGES;
    const int tid = threadIdx.x, wid = tid >> 5, lane = tid & 31;
    const int hb = blockIdx.x * 128, mb = blockIdx.y * 128;
    const int wm = (wid >> 2) * 64, wn = (wid & 3) * 32;

    // stage the per-expert combined bias slice for this CTA
#pragma unroll
    for (int i = tid; i < NE * 128; i += 256)
        dsm[i] = g_dcomb[(size_t)(i >> 7) * NH + hb + (i & 127)];

    load_chunk(0, sb + 0 * STAGE, mb, hb, tid); cp_commit();
    load_chunk(1, sb + 1 * STAGE, mb, hb, tid); cp_commit();
    load_chunk(2, sb + 2 * STAGE, mb, hb, tid); cp_commit();

    float acc[4][4][4], oacc[4][4][4];
#pragma unroll
    for (int a = 0; a < 4; a++)
#pragma unroll
        for (int b = 0; b < 4; b++)
#pragma unroll
            for (int c = 0; c < 4; c++) { acc[a][b][c] = 0.f; oacc[a][b][c] = 0.f; }

    for (int gc = 0; gc < 128; gc++) {
        cp_wait2();
        __syncthreads();

        // issue next prefetch FIRST so cp.async overlaps with this chunk's math.
        // Target stage (gc+3)%4 differs from compute stage gc%4; its previous
        // contents (chunk gc-1) were consumed before the barrier above.
        if (gc + 3 < 128) load_chunk(gc + 3, sb + (u32)((gc + 3) & 3) * STAGE, mb, hb, tid);
        cp_commit();

        u32 st = sb + (u32)(gc & 3) * STAGE;
        u32 Ah = st, Bh = st + TILE, Bl = st + 2 * TILE;

#pragma unroll
        for (int ks = 0; ks < 4; ks++) {
            u32 ah[4][4], bh[4][2], bl[4][2];
            u32 arel = swz128((u32)((lane & 15) * 128 + ks * 32 + (lane >> 4) * 16));
#pragma unroll
            for (int mt = 0; mt < 4; mt++) {
                u32 ao = (u32)((wm + mt * 16) * 128) + arel;
                ldsm4(ah[mt][0], ah[mt][1], ah[mt][2], ah[mt][3], Ah + ao);
            }
            u32 brel = swz128((u32)((lane & 7) * 128 + ks * 32 + ((lane >> 3) & 1) * 16));
#pragma unroll
            for (int pr = 0; pr < 2; pr++) {
                u32 bo = (u32)((wn + pr * 16 + ((lane >> 4) & 1) * 8) * 128) + brel;
                ldsm4(bh[pr * 2][0], bh[pr * 2][1], bh[pr * 2 + 1][0], bh[pr * 2 + 1][1], Bh + bo);
                ldsm4(bl[pr * 2][0], bl[pr * 2][1], bl[pr * 2 + 1][0], bl[pr * 2 + 1][1], Bl + bo);
            }
#pragma unroll
            for (int mt = 0; mt < 4; mt++)
#pragma unroll
                for (int nt = 0; nt < 4; nt++) {
                    mma16816(acc[mt][nt], ah[mt], bh[nt]);   // x_hi * w_hi
                    mma16816(acc[mt][nt], ah[mt], bl[nt]);   // x_hi * w_lo
                }
        }

        if ((gc & 7) == 7) {    // finished expert e: rescale + relu + accumulate
            int e = gc >> 3;
            const float2* dp = (const float2*)(dsm + e * 128 + wn);
#pragma unroll
            for (int nt = 0; nt < 4; nt++) {
                float2 d2 = dp[nt * 4 + (lane & 3)];
#pragma unroll
                for (int mt = 0; mt < 4; mt++) {
                    oacc[mt][nt][0] += fmaxf(fmaf(acc[mt][nt][0], INV_WSCALE, d2.x), 0.f);
                    oacc[mt][nt][1] += fmaxf(fmaf(acc[mt][nt][1], INV_WSCALE, d2.y), 0.f);
                    oacc[mt][nt][2] += fmaxf(fmaf(acc[mt][nt][2], INV_WSCALE, d2.x), 0.f);
                    oacc[mt][nt][3] += fmaxf(fmaf(acc[mt][nt][3], INV_WSCALE, d2.y), 0.f);
                    acc[mt][nt][0] = 0.f; acc[mt][nt][1] = 0.f;
                    acc[mt][nt][2] = 0.f; acc[mt][nt][3] = 0.f;
                }
            }
        }
    }

    // store: C fragment mapping — (row t/4 [+8], col 2*(t%4) [+1])
#pragma unroll
    for (int mt = 0; mt < 4; mt++)
#pragma unroll
        for (int nt = 0; nt < 4; nt++) {
            int r0 = mb + wm + mt * 16 + (lane >> 2);
            int cc = hb + wn + nt * 8 + 2 * (lane & 3);
            *(float2*)(out + (size_t)r0 * NH + cc) =
                make_float2(oacc[mt][nt][0], oacc[mt][nt][1]);
            *(float2*)(out + (size_t)(r0 + 8) * NH + cc) =
                make_float2(oacc[mt][nt][2], oacc[mt][nt][3]);
        }
}

// ---------------- launch -----------------------------------------------------
extern "C" void kernel_launch(void* const* d_in, const int* in_sizes, int n_in,
                              void* d_out, int out_size) {
    const float* x       = (const float*)d_in[0];  // [B, D]
    const float* centers = (const float*)d_in[1];  // [E, D]
    const float* W       = (const float*)d_in[2];  // [E, H, D]
    const float* bias    = (const float*)d_in[3];  // [E, H]
    float* out = (float*)d_out;                    // [B, H]

    cudaFuncSetAttribute(gemm_kernel, cudaFuncAttributeMaxDynamicSharedMemorySize, SMEM_TOTAL);

    x_split_kernel<<<(NB * ND / 4) / 256, 256>>>(x);
    w_split_bias_kernel<<<(NE * NH) / 8, 256>>>(W, centers, bias);

    dim3 grid(NH / 128, NB / 128);   // (16, 32)
    gemm_kernel<<<grid, 256, SMEM_TOTAL>>>(out);
}

// round 5
// speedup vs baseline: 9.2795x; 1.6634x over previous
#include <cuda_runtime.h>
#include <cuda_fp16.h>
#include <cstdint>

typedef unsigned long long u64;
typedef uint32_t u32;

#define NB 4096
#define NE 16
#define ND 512
#define NH 2048

#define KC 64                          // k-chunk: 64 fp16 = 128B rows
#define TILE 16384                     // 128 x 64 fp16 tile bytes
#define STAGE (2 * TILE)               // xh, wh
#define NSTAGE 5
#define OFF_STAGES 8192                // after d-table (16*128 floats)
#define SMEM_TOTAL (OFF_STAGES + NSTAGE * STAGE)   // 172032 B

// ---------------- scratch (device globals; no allocations allowed) ----------
__device__ __half g_xh[NB * ND];
__device__ __half g_wh[NE * NH * ND];
__device__ float  g_dcomb[NE * NH];

// ---------------- PTX helpers ----------------------------------------------
__device__ __forceinline__ u32 smem_u32(const void* p) {
    u32 a;
    asm("{ .reg .u64 t; cvta.to.shared.u64 t, %1; cvt.u32.u64 %0, t; }" : "=r"(a) : "l"(p));
    return a;
}
__device__ __forceinline__ void cp16(u32 dst, const void* src) {
    asm volatile("cp.async.cg.shared.global [%0], [%1], 16;" :: "r"(dst), "l"(src) : "memory");
}
__device__ __forceinline__ void cp_commit() { asm volatile("cp.async.commit_group;" ::: "memory"); }
__device__ __forceinline__ void cp_wait3()  { asm volatile("cp.async.wait_group 3;" ::: "memory"); }

__device__ __forceinline__ void ldsm4(u32& r0, u32& r1, u32& r2, u32& r3, u32 addr) {
    asm volatile("ldmatrix.sync.aligned.m8n8.x4.shared.b16 {%0,%1,%2,%3}, [%4];"
                 : "=r"(r0), "=r"(r1), "=r"(r2), "=r"(r3) : "r"(addr));
}
__device__ __forceinline__ void mma16816(float* c, const u32* a, const u32* b) {
    asm volatile("mma.sync.aligned.m16n8k16.row.col.f32.f16.f16.f32 "
                 "{%0,%1,%2,%3}, {%4,%5,%6,%7}, {%8,%9}, {%0,%1,%2,%3};"
                 : "+f"(c[0]), "+f"(c[1]), "+f"(c[2]), "+f"(c[3])
                 : "r"(a[0]), "r"(a[1]), "r"(a[2]), "r"(a[3]), "r"(b[0]), "r"(b[1]));
}

__device__ __forceinline__ u32 swz128(u32 off) { return off ^ ((off >> 3) & 0x70); }

// ---------------- prep kernels ----------------------------------------------
__global__ void x_conv_kernel(const float* __restrict__ x) {
    int i = blockIdx.x * blockDim.x + threadIdx.x;
    float4 v = ((const float4*)x)[i];
    __half2* ph = (__half2*)g_xh;
    ph[2 * i]     = __half2(__float2half_rn(v.x), __float2half_rn(v.y));
    ph[2 * i + 1] = __half2(__float2half_rn(v.z), __float2half_rn(v.w));
}

// one warp per (e,h) row: W row -> fp16, and d = bias - c_e . W_row (fp32)
__global__ void w_conv_bias_kernel(const float* __restrict__ W,
                                   const float* __restrict__ centers,
                                   const float* __restrict__ bias) {
    int gw   = (blockIdx.x * blockDim.x + threadIdx.x) >> 5;
    int lane = threadIdx.x & 31;
    if (gw >= NE * NH) return;
    int e = gw >> 11;
    const float4* wr = (const float4*)(W + (size_t)gw * ND);
    const float4* cr = (const float4*)(centers + (size_t)e * ND);
    __half2* ph = (__half2*)(g_wh + (size_t)gw * ND);
    float s = 0.f;
#pragma unroll
    for (int i = 0; i < ND / 128; i++) {
        int idx = lane + 32 * i;
        float4 w4 = wr[idx];
        float4 c4 = cr[idx];
        s += w4.x * c4.x + w4.y * c4.y + w4.z * c4.z + w4.w * c4.w;
        ph[2 * idx]     = __half2(__float2half_rn(w4.x), __float2half_rn(w4.y));
        ph[2 * idx + 1] = __half2(__float2half_rn(w4.z), __float2half_rn(w4.w));
    }
#pragma unroll
    for (int o = 16; o; o >>= 1) s += __shfl_xor_sync(0xffffffffu, s, o);
    if (lane == 0) g_dcomb[gw] = bias[gw] - s;
}

// ---------------- main GEMM kernel -------------------------------------------
// grid (NH/128, NB/128) = (16, 32); 256 threads, 8 warps (2m x 4n of 64x32).
// 128 chunks = 16 experts x 8 k-chunks of 64. One fp16 MMA per (k16, mt, nt).

__device__ __forceinline__ void load_chunk(int gc, u32 dst, int mb, int hb, int tid) {
    int e = gc >> 3, kc = (gc & 7) * KC;
    int row = tid >> 3, c = tid & 7;
    u32 so = swz128((u32)(row * 128 + c * 16));
    const __half* pxh = g_xh + (size_t)(mb + row) * ND + kc + c * 8;
    const __half* pwh = g_wh + (size_t)(e * NH + hb + row) * ND + kc + c * 8;
#pragma unroll
    for (int i = 0; i < 4; i++) {
        u32 d = dst + so + (u32)i * 4096;          // +32 rows per step
        size_t eo = (size_t)(32 * i) * ND;
        cp16(d + 0 * TILE, pxh + eo);
        cp16(d + 1 * TILE, pwh + eo);
    }
}

__global__ void __launch_bounds__(256, 1)
gemm_kernel(float* __restrict__ out) {
    extern __shared__ char smem[];
    float* dsm = (float*)smem;                     // [16][128] combined bias
    u32 sb = smem_u32(smem) + OFF_STAGES;
    const int tid = threadIdx.x, wid = tid >> 5, lane = tid & 31;
    const int hb = blockIdx.x * 128, mb = blockIdx.y * 128;
    const int wm = (wid >> 2) * 64, wn = (wid & 3) * 32;

    // stage the per-expert combined bias slice for this CTA
#pragma unroll
    for (int i = tid; i < NE * 128; i += 256)
        dsm[i] = g_dcomb[(size_t)(i >> 7) * NH + hb + (i & 127)];

    load_chunk(0, sb + 0 * STAGE, mb, hb, tid); cp_commit();
    load_chunk(1, sb + 1 * STAGE, mb, hb, tid); cp_commit();
    load_chunk(2, sb + 2 * STAGE, mb, hb, tid); cp_commit();
    load_chunk(3, sb + 3 * STAGE, mb, hb, tid); cp_commit();

    float acc[4][4][4], oacc[4][4][4];
#pragma unroll
    for (int a = 0; a < 4; a++)
#pragma unroll
        for (int b = 0; b < 4; b++)
#pragma unroll
            for (int c = 0; c < 4; c++) { acc[a][b][c] = 0.f; oacc[a][b][c] = 0.f; }

    int st_idx = 0, pf_idx = 4;
    for (int gc = 0; gc < 128; gc++) {
        cp_wait3();
        __syncthreads();

        // issue next prefetch FIRST so cp.async overlaps with this chunk's math.
        if (gc + 4 < 128) load_chunk(gc + 4, sb + (u32)pf_idx * STAGE, mb, hb, tid);
        cp_commit();
        pf_idx = (pf_idx == NSTAGE - 1) ? 0 : pf_idx + 1;

        u32 st = sb + (u32)st_idx * STAGE;
        st_idx = (st_idx == NSTAGE - 1) ? 0 : st_idx + 1;
        u32 Ah = st, Bh = st + TILE;

#pragma unroll
        for (int ks = 0; ks < 4; ks++) {
            u32 ah[4][4], bh[4][2];
            u32 arel = swz128((u32)((lane & 15) * 128 + ks * 32 + (lane >> 4) * 16));
#pragma unroll
            for (int mt = 0; mt < 4; mt++) {
                u32 ao = (u32)((wm + mt * 16) * 128) + arel;
                ldsm4(ah[mt][0], ah[mt][1], ah[mt][2], ah[mt][3], Ah + ao);
            }
            u32 brel = swz128((u32)((lane & 7) * 128 + ks * 32 + ((lane >> 3) & 1) * 16));
#pragma unroll
            for (int pr = 0; pr < 2; pr++) {
                u32 bo = (u32)((wn + pr * 16 + ((lane >> 4) & 1) * 8) * 128) + brel;
                ldsm4(bh[pr * 2][0], bh[pr * 2][1], bh[pr * 2 + 1][0], bh[pr * 2 + 1][1], Bh + bo);
            }
#pragma unroll
            for (int mt = 0; mt < 4; mt++)
#pragma unroll
                for (int nt = 0; nt < 4; nt++)
                    mma16816(acc[mt][nt], ah[mt], bh[nt]);
        }

        if ((gc & 7) == 7) {    // finished expert e: relu + accumulate, reset
            int e = gc >> 3;
            const float2* dp = (const float2*)(dsm + e * 128 + wn);
#pragma unroll
            for (int nt = 0; nt < 4; nt++) {
                float2 d2 = dp[nt * 4 + (lane & 3)];
#pragma unroll
                for (int mt = 0; mt < 4; mt++) {
                    oacc[mt][nt][0] += fmaxf(acc[mt][nt][0] + d2.x, 0.f);
                    oacc[mt][nt][1] += fmaxf(acc[mt][nt][1] + d2.y, 0.f);
                    oacc[mt][nt][2] += fmaxf(acc[mt][nt][2] + d2.x, 0.f);
                    oacc[mt][nt][3] += fmaxf(acc[mt][nt][3] + d2.y, 0.f);
                    acc[mt][nt][0] = 0.f; acc[mt][nt][1] = 0.f;
                    acc[mt][nt][2] = 0.f; acc[mt][nt][3] = 0.f;
                }
            }
        }
    }

    // store: C fragment mapping — (row t/4 [+8], col 2*(t%4) [+1])
#pragma unroll
    for (int mt = 0; mt < 4; mt++)
#pragma unroll
        for (int nt = 0; nt < 4; nt++) {
            int r0 = mb + wm + mt * 16 + (lane >> 2);
            int cc = hb + wn + nt * 8 + 2 * (lane & 3);
            *(float2*)(out + (size_t)r0 * NH + cc) =
                make_float2(oacc[mt][nt][0], oacc[mt][nt][1]);
            *(float2*)(out + (size_t)(r0 + 8) * NH + cc) =
                make_float2(oacc[mt][nt][2], oacc[mt][nt][3]);
        }
}

// ---------------- launch -----------------------------------------------------
extern "C" void kernel_launch(void* const* d_in, const int* in_sizes, int n_in,
                              void* d_out, int out_size) {
    const float* x       = (const float*)d_in[0];  // [B, D]
    const float* centers = (const float*)d_in[1];  // [E, D]
    const float* W       = (const float*)d_in[2];  // [E, H, D]
    const float* bias    = (const float*)d_in[3];  // [E, H]
    float* out = (float*)d_out;                    // [B, H]

    cudaFuncSetAttribute(gemm_kernel, cudaFuncAttributeMaxDynamicSharedMemorySize, SMEM_TOTAL);

    x_conv_kernel<<<(NB * ND / 4) / 256, 256>>>(x);
    w_conv_bias_kernel<<<(NE * NH) / 8, 256>>>(W, centers, bias);

    dim3 grid(NH / 128, NB / 128);   // (16, 32)
    gemm_kernel<<<grid, 256, SMEM_TOTAL>>>(out);
}